// round 11
// baseline (speedup 1.0000x reference)
#include <cuda_runtime.h>

// out[b,t,d] = x[b,t,d] * (sum_{k<t} x[b,k,d])
// B=8, T=4096, D=1024, fp32.
// Single-pass, register-staged. CHUNK=8 keeps regs <= 42 so 6 CTAs co-reside
// per SM: independent CTAs' load and scan/emit phases interleave, keeping
// LDGs in flight continuously. DRAM traffic = 1 read + 1 write = 268 MB.

#define T_DIM   4096
#define D_DIM   1024
#define D_TILE  16
#define SLICES  16
#define CHUNK   8                        // t-steps per thread per stage
#define STAGE_T (SLICES * CHUNK)         // 128
#define NSTAGE  (T_DIM / STAGE_T)        // 32
#define NTHREADS (D_TILE * SLICES)       // 256

__global__ __launch_bounds__(NTHREADS, 6)
void siso_scan_reg6(const float* __restrict__ x, float* __restrict__ out) {
    __shared__ float ssum[SLICES][D_TILE + 1];  // [slice][d], stride 17
    __shared__ float carry[D_TILE];             // running prefix per d-lane

    const int tid    = threadIdx.x;
    const int lane_d = tid & (D_TILE - 1);      // d within tile (0..15)
    const int slice  = tid >> 4;                // t-slice (0..15)
    const int wid    = tid >> 5;                // warp id (0..7)
    const int lid    = tid & 31;

    const int d_tiles = D_DIM / D_TILE;         // 64
    const int d_tile  = blockIdx.x & (d_tiles - 1);
    const int b       = blockIdx.x >> 6;        // blockIdx.x / 64

    const unsigned base = (unsigned)b * (T_DIM * D_DIM)
                        + (unsigned)d_tile * D_TILE + (unsigned)lane_d;

    if (tid < D_TILE) carry[tid] = 0.f;
    __syncthreads();

    for (int st = 0; st < NSTAGE; ++st) {
        const unsigned t_base = (unsigned)st * STAGE_T + (unsigned)slice * CHUNK;
        const float* __restrict__ p = x   + base + t_base * D_DIM;
        float*       __restrict__ q = out + base + t_base * D_DIM;

        // Load chunk into registers (8 independent LDGs), chunk sum.
        float v[CHUNK];
        float s = 0.f;
        #pragma unroll
        for (int i = 0; i < CHUNK; ++i) {
            v[i] = p[(unsigned)i * D_DIM];
            s += v[i];
        }
        ssum[slice][lane_d] = s;
        __syncthreads();

        // Segmented shuffle scan: each warp scans two d-columns' 16 slice
        // sums (16-lane segments). stride-17 smem -> conflict-free.
        {
            const int d0    = (wid << 1) + (lid >> 4);   // d-column for this lane
            const int s_idx = lid & 15;                  // slice index in column
            float val  = ssum[s_idx][d0];
            float incl = val;
            #pragma unroll
            for (int off = 1; off < 16; off <<= 1) {
                float n = __shfl_up_sync(0xFFFFFFFFu, incl, off);
                if (s_idx >= off) incl += n;
            }
            float c = carry[d0];
            ssum[s_idx][d0] = (incl - val) + c;          // exclusive + carry-in
            if (s_idx == 15) carry[d0] = incl + c;       // carry-out
        }
        __syncthreads();

        // Emit from registers; next stage's loads can issue while stores drain.
        float run = ssum[slice][lane_d];
        #pragma unroll
        for (int i = 0; i < CHUNK; ++i) {
            q[(unsigned)i * D_DIM] = v[i] * run;
            run += v[i];
        }
        // ssum/carry are only rewritten after the next in-loop __syncthreads().
    }
}

extern "C" void kernel_launch(void* const* d_in, const int* in_sizes, int n_in,
                              void* d_out, int out_size) {
    const float* x = (const float*)d_in[0];
    float* out = (float*)d_out;

    const int n = in_sizes[0];                    // B*T*D
    const int B = n / (T_DIM * D_DIM);            // 8
    const int blocks = B * (D_DIM / D_TILE);      // 512

    siso_scan_reg6<<<blocks, NTHREADS>>>(x, out);
}

// round 12
// speedup vs baseline: 1.4792x; 1.4792x over previous
#include <cuda_runtime.h>

// out[b,t,d] = x[b,t,d] * (sum_{k<t} x[b,k,d])
// B=8, T=4096, D=1024, fp32.
// Single-pass, register-staged, float2-vectorized (each thread owns 2
// consecutive d). R10 skeleton: 256-thread blocks, CHUNK=16, 4 CTAs/SM for
// phase interleaving. DRAM traffic = 1 read + 1 write = 268 MB.

#define T_DIM   4096
#define D_DIM   1024
#define VLANES  8                        // float2 lanes per slice-row
#define D_TILE  (VLANES * 2)             // 16 d per block
#define SLICES  32
#define CHUNK   16                       // t-steps per thread per stage
#define STAGE_T (SLICES * CHUNK)         // 512
#define NSTAGE  (T_DIM / STAGE_T)        // 8
#define NTHREADS (VLANES * SLICES)       // 256
#define ROW2    (D_DIM / 2)              // row stride in float2 units

__global__ __launch_bounds__(NTHREADS, 4)
void siso_scan_v2(const float2* __restrict__ x, float2* __restrict__ out) {
    __shared__ float ssum[SLICES][D_TILE + 1];  // [slice][d], stride 17
    __shared__ float carry[D_TILE];             // running prefix per d

    const int tid    = threadIdx.x;
    const int lane_v = tid & (VLANES - 1);      // float2 lane (0..7)
    const int slice  = tid >> 3;                // t-slice (0..31)
    const int wid    = tid >> 5;                // warp id (0..7)
    const int lid    = tid & 31;

    const int d_tiles = D_DIM / D_TILE;         // 64
    const int d_tile  = blockIdx.x & (d_tiles - 1);
    const int b       = blockIdx.x >> 6;

    // base in float2 units
    const unsigned base = (unsigned)b * (T_DIM * ROW2)
                        + (unsigned)d_tile * VLANES + (unsigned)lane_v;

    if (tid < D_TILE) carry[tid] = 0.f;
    __syncthreads();

    for (int st = 0; st < NSTAGE; ++st) {
        const unsigned t_base = (unsigned)st * STAGE_T + (unsigned)slice * CHUNK;
        const float2* __restrict__ p = x   + base + t_base * ROW2;
        float2*       __restrict__ q = out + base + t_base * ROW2;

        // Load chunk into registers (16 independent LDG.64), chunk sums.
        float2 v[CHUNK];
        float sx = 0.f, sy = 0.f;
        #pragma unroll
        for (int i = 0; i < CHUNK; ++i) {
            v[i] = p[(unsigned)i * ROW2];
            sx += v[i].x;
            sy += v[i].y;
        }
        ssum[slice][lane_v * 2]     = sx;
        ssum[slice][lane_v * 2 + 1] = sy;
        __syncthreads();

        // Each warp shuffle-scans 2 d-columns (32 slice sums each).
        // stride-17 smem -> lid*17 mod 32 distinct -> conflict-free.
        #pragma unroll
        for (int cc = 0; cc < 2; ++cc) {
            const int col = wid * 2 + cc;
            float val  = ssum[lid][col];
            float incl = val;
            #pragma unroll
            for (int off = 1; off < 32; off <<= 1) {
                float n = __shfl_up_sync(0xFFFFFFFFu, incl, off);
                if (lid >= off) incl += n;
            }
            float c = carry[col];
            ssum[lid][col] = (incl - val) + c;       // exclusive + carry-in
            if (lid == 31) carry[col] = incl + c;    // carry-out
        }
        __syncthreads();

        // Emit from registers (16 STG.64); next stage's loads overlap drain.
        float rx = ssum[slice][lane_v * 2];
        float ry = ssum[slice][lane_v * 2 + 1];
        #pragma unroll
        for (int i = 0; i < CHUNK; ++i) {
            float2 o;
            o.x = v[i].x * rx;
            o.y = v[i].y * ry;
            q[(unsigned)i * ROW2] = o;
            rx += v[i].x;
            ry += v[i].y;
        }
        // ssum/carry only rewritten after the next in-loop __syncthreads().
    }
}

extern "C" void kernel_launch(void* const* d_in, const int* in_sizes, int n_in,
                              void* d_out, int out_size) {
    const float2* x = (const float2*)d_in[0];
    float2* out = (float2*)d_out;

    const int n = in_sizes[0];                    // B*T*D
    const int B = n / (T_DIM * D_DIM);            // 8
    const int blocks = B * (D_DIM / D_TILE);      // 512

    siso_scan_v2<<<blocks, NTHREADS>>>(x, out);
}